// round 12
// baseline (speedup 1.0000x reference)
#include <cuda_runtime.h>
#include <cuda_fp16.h>
#include <cstddef>
#include <cstdint>

#define D 64
#define NMAX 100000
#define EMAX 1300000
#define HP 36   // half2 pitch per row: bank = 4*gid + tg -> conflict-free

// Scratch (no allocation allowed -> device globals)
__device__ float  g_h[(size_t)NMAX * D];
__device__ float  g_t2[(size_t)NMAX * D];
__device__ float  g_stats[5 * 2 * D];
__device__ int    g_deg[NMAX];
__device__ int    g_ptr[NMAX + 1];
__device__ int    g_cur[NMAX];
__device__ int    g_csr[EMAX];

// ---------------------------------------------------------------------------
__global__ void zero_kernel(int n) {
    int i = blockIdx.x * blockDim.x + threadIdx.x;
    if (i < 5 * 2 * D) g_stats[i] = 0.f;
    if (i < n) g_deg[i] = 0;
}
__global__ void hist_kernel(const int* __restrict__ ei, int E) {
    int e = blockIdx.x * blockDim.x + threadIdx.x;
    if (e < E) atomicAdd(g_deg + __ldg(ei + E + e), 1);
}

// single-block exclusive scan of g_deg -> g_ptr/g_cur (1024 thr, 4096/chunk)
__global__ void __launch_bounds__(1024, 1) scan_kernel(int n, int E) {
    __shared__ int wsum[32];
    int t = threadIdx.x, lane = t & 31, w = t >> 5;
    int carry = 0;
    for (int base = 0; base < n; base += 4096) {
        int idx = base + t * 4;
        int v0 = 0, v1 = 0, v2 = 0, v3 = 0;
        if (idx + 0 < n) v0 = g_deg[idx + 0];
        if (idx + 1 < n) v1 = g_deg[idx + 1];
        if (idx + 2 < n) v2 = g_deg[idx + 2];
        if (idx + 3 < n) v3 = g_deg[idx + 3];
        int s = v0 + v1 + v2 + v3;
        int sc = s;
#pragma unroll
        for (int o = 1; o < 32; o <<= 1) {
            int x = __shfl_up_sync(0xffffffffu, sc, o);
            if (lane >= o) sc += x;
        }
        if (lane == 31) wsum[w] = sc;
        __syncthreads();
        if (w == 0) {
            int ws = wsum[lane];
#pragma unroll
            for (int o = 1; o < 32; o <<= 1) {
                int x = __shfl_up_sync(0xffffffffu, ws, o);
                if (lane >= o) ws += x;
            }
            wsum[lane] = ws;
        }
        __syncthreads();
        int excl = sc - s + (w ? wsum[w - 1] : 0) + carry;
        if (idx + 0 < n) { g_ptr[idx + 0] = excl;                 g_cur[idx + 0] = excl; }
        if (idx + 1 < n) { g_ptr[idx + 1] = excl + v0;            g_cur[idx + 1] = excl + v0; }
        if (idx + 2 < n) { g_ptr[idx + 2] = excl + v0 + v1;       g_cur[idx + 2] = excl + v0 + v1; }
        if (idx + 3 < n) { g_ptr[idx + 3] = excl + v0 + v1 + v2;  g_cur[idx + 3] = excl + v0 + v1 + v2; }
        carry += wsum[31];
        __syncthreads();
    }
    if (t == 0) g_ptr[n] = E;
}
__global__ void fill_kernel(const int* __restrict__ ei, int E) {
    int e = blockIdx.x * blockDim.x + threadIdx.x;
    if (e >= E) return;
    int src = __ldg(ei + e);
    int dst = __ldg(ei + E + e);
    int pos = atomicAdd(g_cur + dst, 1);
    g_csr[pos] = src;
}

// ---------------------------------------------------------------------------
// fp16 split helpers (hi/lo -> ~2^-22 combined mantissa)
__device__ __forceinline__ void split_h2(float x, float y, uint32_t& hi, uint32_t& lo) {
    __half hx = __float2half_rn(x), hy = __float2half_rn(y);
    __half lx = __float2half_rn(x - __half2float(hx));
    __half ly = __float2half_rn(y - __half2float(hy));
    __half2 h = __halves2half2(hx, hy), l = __halves2half2(lx, ly);
    hi = *(uint32_t*)&h; lo = *(uint32_t*)&l;
}
__device__ __forceinline__ void mma_f16(float* c, const uint32_t* a, const uint32_t* b) {
    asm volatile(
        "mma.sync.aligned.m16n8k16.row.col.f32.f16.f16.f32 "
        "{%0,%1,%2,%3}, {%4,%5,%6,%7}, {%8,%9}, {%0,%1,%2,%3};"
        : "+f"(c[0]), "+f"(c[1]), "+f"(c[2]), "+f"(c[3])
        : "r"(a[0]), "r"(a[1]), "r"(a[2]), "r"(a[3]), "r"(b[0]), "r"(b[1]));
}

__device__ __forceinline__ void load_wfrags(
    const float* __restrict__ W, int wn, int gid, int tg,
    uint32_t wh[2][4][2], uint32_t wl[2][4][2])
{
#pragma unroll
    for (int nt = 0; nt < 2; nt++) {
        int col = wn * 16 + nt * 8 + gid;
#pragma unroll
        for (int s = 0; s < 4; s++) {
            int k0 = s * 16 + 2 * tg;
            float w0 = __ldg(W + (k0 + 0) * 64 + col);
            float w1 = __ldg(W + (k0 + 1) * 64 + col);
            float w2 = __ldg(W + (k0 + 8) * 64 + col);
            float w3 = __ldg(W + (k0 + 9) * 64 + col);
            split_h2(w0, w1, wh[nt][s][0], wl[nt][s][0]);
            split_h2(w2, w3, wh[nt][s][1], wl[nt][s][1]);
        }
    }
}

__device__ __forceinline__ void gemm_f16x2(
    const uint32_t* __restrict__ sAh, const uint32_t* __restrict__ sAl,
    int wm, int gid, int tg,
    const uint32_t wh[2][4][2], const uint32_t wl[2][4][2],
    float acc[2][2][4])
{
#pragma unroll
    for (int s = 0; s < 4; s++) {
        uint32_t ah[2][4], al[2][4];
#pragma unroll
        for (int mt = 0; mt < 2; mt++) {
            int r = wm * 32 + mt * 16 + gid;
            int kb = s * 8 + tg;
            ah[mt][0] = sAh[r * HP + kb];
            ah[mt][1] = sAh[(r + 8) * HP + kb];
            ah[mt][2] = sAh[r * HP + kb + 4];
            ah[mt][3] = sAh[(r + 8) * HP + kb + 4];
            al[mt][0] = sAl[r * HP + kb];
            al[mt][1] = sAl[(r + 8) * HP + kb];
            al[mt][2] = sAl[r * HP + kb + 4];
            al[mt][3] = sAl[(r + 8) * HP + kb + 4];
        }
#pragma unroll
        for (int mt = 0; mt < 2; mt++)
#pragma unroll
            for (int nt = 0; nt < 2; nt++) {
                mma_f16(acc[mt][nt], ah[mt], wh[nt][s]);
                mma_f16(acc[mt][nt], al[mt], wh[nt][s]);
                mma_f16(acc[mt][nt], ah[mt], wl[nt][s]);
            }
    }
}

// shared epilogue: bias + relu + store + BN-stat atomics
__device__ __forceinline__ void epilogue(
    float acc[2][2][4], const float* __restrict__ bias,
    float* __restrict__ outF, float* __restrict__ stats,
    int row0, int wm, int wn, int gid, int tg, int nrows)
{
    float cs[2][2] = {{0.f, 0.f}, {0.f, 0.f}};
    float cq[2][2] = {{0.f, 0.f}, {0.f, 0.f}};
#pragma unroll
    for (int nt = 0; nt < 2; nt++) {
        int cb = wn * 16 + nt * 8 + 2 * tg;
        float bx = __ldg(bias + cb), by = __ldg(bias + cb + 1);
#pragma unroll
        for (int mt = 0; mt < 2; mt++) {
#pragma unroll
            for (int hh = 0; hh < 2; hh++) {
                int gr = row0 + wm * 32 + mt * 16 + gid + hh * 8;
                if (gr < nrows) {
                    float ox = fmaxf(acc[mt][nt][2 * hh + 0] + bx, 0.f);
                    float oy = fmaxf(acc[mt][nt][2 * hh + 1] + by, 0.f);
                    *(float2*)(outF + (size_t)gr * D + cb) = make_float2(ox, oy);
                    cs[nt][0] += ox; cq[nt][0] += ox * ox;
                    cs[nt][1] += oy; cq[nt][1] += oy * oy;
                }
            }
        }
    }
#pragma unroll
    for (int off = 4; off < 32; off <<= 1) {
#pragma unroll
        for (int nt = 0; nt < 2; nt++)
#pragma unroll
            for (int j = 0; j < 2; j++) {
                cs[nt][j] += __shfl_xor_sync(0xffffffffu, cs[nt][j], off);
                cq[nt][j] += __shfl_xor_sync(0xffffffffu, cq[nt][j], off);
            }
    }
    if (gid == 0) {
#pragma unroll
        for (int nt = 0; nt < 2; nt++) {
            int c = wn * 16 + nt * 8 + 2 * tg;
            atomicAdd(stats + c,         cs[nt][0]);
            atomicAdd(stats + c + 1,     cs[nt][1]);
            atomicAdd(stats + D + c,     cq[nt][0]);
            atomicAdd(stats + D + c + 1, cq[nt][1]);
        }
    }
}

// ---------------------------------------------------------------------------
// Fused gather + 2-layer MLP via split-fp16 tensor-core GEMM.
__global__ void __launch_bounds__(256, 3) mlp_kernel(
    const float* __restrict__ feat,
    const float* __restrict__ pstats, const float* __restrict__ pg,
    const float* __restrict__ pb,
    const float* __restrict__ W1, const float* __restrict__ b1,
    const float* __restrict__ W2, const float* __restrict__ b2,
    float* __restrict__ outF,
    float* __restrict__ stats, float invN, int nrows)
{
    __shared__ uint32_t sAh[64 * HP];
    __shared__ uint32_t sAl[64 * HP];
    __shared__ float    sAff[2 * D];

    const int t = threadIdx.x;
    const int lane = t & 31, wid = t >> 5;
    const int wm = wid & 1, wn = wid >> 1;
    const int gid = lane >> 2, tg = lane & 3;
    const int row0 = blockIdx.x * 64;
    const bool useAff = (pstats != nullptr);

    if (useAff && t < D) {
        float m  = pstats[t] * invN;
        float var = pstats[D + t] * invN - m * m;
        float sc = pg[t] * rsqrtf(var + 1e-5f);
        sAff[t]     = sc;
        sAff[D + t] = pb[t] - m * sc;
    }
    if (useAff) __syncthreads();

    // fused CSR gather from fp32 features, 16 lanes/node, 8x pipelined
#pragma unroll
    for (int pass = 0; pass < 4; pass++) {
        int r = pass * 16 + (t >> 4);
        int node = row0 + r;
        int c4 = (t & 15) << 2;
        float4 acc = make_float4(0.f, 0.f, 0.f, 0.f);
        if (node < nrows) {
            acc = *(const float4*)(feat + (size_t)node * D + c4);
            int s = __ldg(g_ptr + node), e = __ldg(g_ptr + node + 1);
            int j = s;
            for (; j + 8 <= e; j += 8) {
                int si[8];
#pragma unroll
                for (int q = 0; q < 8; q++) si[q] = __ldg(g_csr + j + q);
                float4 v[8];
#pragma unroll
                for (int q = 0; q < 8; q++)
                    v[q] = *(const float4*)(feat + (size_t)si[q] * D + c4);
                float4 a0, a1;
                a0.x = v[0].x + v[1].x; a0.y = v[0].y + v[1].y;
                a0.z = v[0].z + v[1].z; a0.w = v[0].w + v[1].w;
                a1.x = v[2].x + v[3].x; a1.y = v[2].y + v[3].y;
                a1.z = v[2].z + v[3].z; a1.w = v[2].w + v[3].w;
                a0.x += v[4].x + v[5].x; a0.y += v[4].y + v[5].y;
                a0.z += v[4].z + v[5].z; a0.w += v[4].w + v[5].w;
                a1.x += v[6].x + v[7].x; a1.y += v[6].y + v[7].y;
                a1.z += v[6].z + v[7].z; a1.w += v[6].w + v[7].w;
                acc.x += a0.x + a1.x; acc.y += a0.y + a1.y;
                acc.z += a0.z + a1.z; acc.w += a0.w + a1.w;
            }
            for (; j + 4 <= e; j += 4) {
                int s0 = __ldg(g_csr + j + 0);
                int s1 = __ldg(g_csr + j + 1);
                int s2 = __ldg(g_csr + j + 2);
                int s3 = __ldg(g_csr + j + 3);
                float4 v0 = *(const float4*)(feat + (size_t)s0 * D + c4);
                float4 v1 = *(const float4*)(feat + (size_t)s1 * D + c4);
                float4 v2 = *(const float4*)(feat + (size_t)s2 * D + c4);
                float4 v3 = *(const float4*)(feat + (size_t)s3 * D + c4);
                acc.x += v0.x + v1.x + v2.x + v3.x;
                acc.y += v0.y + v1.y + v2.y + v3.y;
                acc.z += v0.z + v1.z + v2.z + v3.z;
                acc.w += v0.w + v1.w + v2.w + v3.w;
            }
            for (; j < e; j++) {
                int sv = __ldg(g_csr + j);
                float4 v = *(const float4*)(feat + (size_t)sv * D + c4);
                acc.x += v.x; acc.y += v.y; acc.z += v.z; acc.w += v.w;
            }
            if (useAff) {
                float cnt = (float)(e - s + 1);
                acc.x = sAff[c4 + 0] * acc.x + cnt * sAff[D + c4 + 0];
                acc.y = sAff[c4 + 1] * acc.y + cnt * sAff[D + c4 + 1];
                acc.z = sAff[c4 + 2] * acc.z + cnt * sAff[D + c4 + 2];
                acc.w = sAff[c4 + 3] * acc.w + cnt * sAff[D + c4 + 3];
            }
        }
        int idx = r * HP + (c4 >> 1);
        split_h2(acc.x, acc.y, sAh[idx], sAl[idx]);
        split_h2(acc.z, acc.w, sAh[idx + 1], sAl[idx + 1]);
    }

    uint32_t wh[2][4][2], wl[2][4][2];
    load_wfrags(W1, wn, gid, tg, wh, wl);

    float acc[2][2][4];
#pragma unroll
    for (int mt = 0; mt < 2; mt++)
#pragma unroll
        for (int nt = 0; nt < 2; nt++)
#pragma unroll
            for (int i = 0; i < 4; i++) acc[mt][nt][i] = 0.f;

    __syncthreads();
    gemm_f16x2(sAh, sAl, wm, gid, tg, wh, wl, acc);

    __syncthreads();
#pragma unroll
    for (int nt = 0; nt < 2; nt++) {
        int cb = wn * 16 + nt * 8 + 2 * tg;
        float bx = __ldg(b1 + cb), by = __ldg(b1 + cb + 1);
        int ci = (cb >> 1);
#pragma unroll
        for (int mt = 0; mt < 2; mt++) {
#pragma unroll
            for (int hh = 0; hh < 2; hh++) {
                int r = wm * 32 + mt * 16 + gid + hh * 8;
                float ox = fmaxf(acc[mt][nt][2 * hh + 0] + bx, 0.f);
                float oy = fmaxf(acc[mt][nt][2 * hh + 1] + by, 0.f);
                split_h2(ox, oy, sAh[r * HP + ci], sAl[r * HP + ci]);
            }
        }
    }
    load_wfrags(W2, wn, gid, tg, wh, wl);
#pragma unroll
    for (int mt = 0; mt < 2; mt++)
#pragma unroll
        for (int nt = 0; nt < 2; nt++)
#pragma unroll
            for (int i = 0; i < 4; i++) acc[mt][nt][i] = 0.f;
    __syncthreads();
    gemm_f16x2(sAh, sAl, wm, gid, tg, wh, wl, acc);

    epilogue(acc, b2, outF, stats, row0, wm, wn, gid, tg, nrows);
}

// ---------------------------------------------------------------------------
// Heads kernel: load t2 tile + BN-3 affine (dense), then BOTH head GEMMs.
__global__ void __launch_bounds__(256, 3) heads_kernel(
    const float* __restrict__ feat,
    const float* __restrict__ pstats, const float* __restrict__ pg,
    const float* __restrict__ pb,
    const float* __restrict__ muW, const float* __restrict__ mub,
    const float* __restrict__ lvW, const float* __restrict__ lvb,
    float* __restrict__ out,
    float* __restrict__ statsMu, float* __restrict__ statsLv,
    float invN, int nrows)
{
    __shared__ uint32_t sAh[64 * HP];
    __shared__ uint32_t sAl[64 * HP];
    __shared__ float    sAff[2 * D];

    const int t = threadIdx.x;
    const int lane = t & 31, wid = t >> 5;
    const int wm = wid & 1, wn = wid >> 1;
    const int gid = lane >> 2, tg = lane & 3;
    const int row0 = blockIdx.x * 64;

    if (t < D) {
        float m  = pstats[t] * invN;
        float var = pstats[D + t] * invN - m * m;
        float sc = pg[t] * rsqrtf(var + 1e-5f);
        sAff[t]     = sc;
        sAff[D + t] = pb[t] - m * sc;
    }
    __syncthreads();

    for (int i = t; i < 1024; i += 256) {
        int r = i >> 4, k4 = (i & 15) << 2;
        float4 v = make_float4(0.f, 0.f, 0.f, 0.f);
        if (row0 + r < nrows) {
            v = *(const float4*)(feat + (size_t)(row0 + r) * D + k4);
            v.x = sAff[k4 + 0] * v.x + sAff[D + k4 + 0];
            v.y = sAff[k4 + 1] * v.y + sAff[D + k4 + 1];
            v.z = sAff[k4 + 2] * v.z + sAff[D + k4 + 2];
            v.w = sAff[k4 + 3] * v.w + sAff[D + k4 + 3];
        }
        int idx = r * HP + (k4 >> 1);
        split_h2(v.x, v.y, sAh[idx], sAl[idx]);
        split_h2(v.z, v.w, sAh[idx + 1], sAl[idx + 1]);
    }

    uint32_t wh[2][4][2], wl[2][4][2];
    float acc[2][2][4];

    // mu head
    load_wfrags(muW, wn, gid, tg, wh, wl);
#pragma unroll
    for (int mt = 0; mt < 2; mt++)
#pragma unroll
        for (int nt = 0; nt < 2; nt++)
#pragma unroll
            for (int i = 0; i < 4; i++) acc[mt][nt][i] = 0.f;
    __syncthreads();
    gemm_f16x2(sAh, sAl, wm, gid, tg, wh, wl, acc);
    epilogue(acc, mub, out, statsMu, row0, wm, wn, gid, tg, nrows);

    // lv head (sA unchanged, read-only)
    load_wfrags(lvW, wn, gid, tg, wh, wl);
#pragma unroll
    for (int mt = 0; mt < 2; mt++)
#pragma unroll
        for (int nt = 0; nt < 2; nt++)
#pragma unroll
            for (int i = 0; i < 4; i++) acc[mt][nt][i] = 0.f;
    gemm_f16x2(sAh, sAl, wm, gid, tg, wh, wl, acc);
    epilogue(acc, lvb, out + (size_t)nrows * D, statsLv,
             row0, wm, wn, gid, tg, nrows);
}

// ---------------------------------------------------------------------------
// final BN for both halves of out, in place
__global__ void bn2_apply_kernel(float* __restrict__ out,
                                 const float* __restrict__ statsMu,
                                 const float* __restrict__ statsLv,
                                 const float* __restrict__ mug,
                                 const float* __restrict__ mubeta,
                                 const float* __restrict__ lvg,
                                 const float* __restrict__ lvbeta,
                                 float invN, int total4)
{
    int i = blockIdx.x * blockDim.x + threadIdx.x;
    if (i >= 2 * total4) return;
    bool isLv = (i >= total4);
    const float* stats = isLv ? statsLv : statsMu;
    const float* g = isLv ? lvg : mug;
    const float* b = isLv ? lvbeta : mubeta;
    int c = (i << 2) & 63;
    float4 v = ((const float4*)out)[i];
    float4 y;
#pragma unroll
    for (int j = 0; j < 4; j++) {
        float m  = stats[c + j] * invN;
        float var = stats[D + c + j] * invN - m * m;
        float sc = g[c + j] * rsqrtf(var + 1e-5f);
        float sh = b[c + j] - m * sc;
        (&y.x)[j] = (&v.x)[j] * sc + sh;
    }
    ((float4*)out)[i] = y;
}

// ---------------------------------------------------------------------------
extern "C" void kernel_launch(void* const* d_in, const int* in_sizes, int n_in,
                              void* d_out, int out_size)
{
    const float* x      = (const float*)d_in[0];
    const int*   ei     = (const int*)d_in[1];   // int32 (JAX downcast)
    const float* W1     = (const float*)d_in[3];
    const float* b1     = (const float*)d_in[4];
    const float* W2     = (const float*)d_in[5];
    const float* b2     = (const float*)d_in[6];
    const float* bng    = (const float*)d_in[7];
    const float* bnb    = (const float*)d_in[8];
    const float* muW    = (const float*)d_in[9];
    const float* mub    = (const float*)d_in[10];
    const float* lvW    = (const float*)d_in[11];
    const float* lvb    = (const float*)d_in[12];
    const float* mug    = (const float*)d_in[13];
    const float* mubeta = (const float*)d_in[14];
    const float* lvg    = (const float*)d_in[15];
    const float* lvbeta = (const float*)d_in[16];
    float* out = (float*)d_out;

    const int n = in_sizes[0] / D;
    const int E = in_sizes[1] / 2;
    const float invN = 1.0f / (float)n;
    const int total4 = n * (D / 4);
    const int gb = (n + 63) / 64;
    const int ebE = (E + 255) / 256;

    float *hbuf, *tbuf, *sbuf;
    cudaGetSymbolAddress((void**)&hbuf, g_h);
    cudaGetSymbolAddress((void**)&tbuf, g_t2);
    cudaGetSymbolAddress((void**)&sbuf, g_stats);

    zero_kernel<<<(n + 255) / 256, 256>>>(n);

    // build CSR (dst -> list of src)
    hist_kernel<<<ebE, 256>>>(ei, E);
    scan_kernel<<<1, 1024>>>(n, E);
    fill_kernel<<<ebE, 256>>>(ei, E);

    // layer 1: gather x, no affine -> t2 (pre-BN, fp32)
    mlp_kernel<<<gb, 256>>>(
        x, nullptr, nullptr, nullptr,
        W1, b1, W2, b2, tbuf, sbuf, invN, n);
    // layer 2: gather t2 + layer-1 affine -> h
    mlp_kernel<<<gb, 256>>>(
        tbuf, sbuf, bng, bnb,
        W1 + 4096, b1 + 64, W2 + 4096, b2 + 64, hbuf, sbuf + 128, invN, n);
    // layer 3: gather h + layer-2 affine -> t2
    mlp_kernel<<<gb, 256>>>(
        hbuf, sbuf + 128, bng + 64, bnb + 64,
        W1 + 8192, b1 + 128, W2 + 8192, b2 + 128, tbuf, sbuf + 256, invN, n);

    // heads: BN-3 affine fused into tile load; both GEMMs; pre-BN -> out
    heads_kernel<<<gb, 256>>>(
        tbuf, sbuf + 256, bng + 128, bnb + 128,
        muW, mub, lvW, lvb, out, sbuf + 3 * 128, sbuf + 4 * 128, invN, n);

    // final BN on both halves (in place)
    bn2_apply_kernel<<<(2 * total4 + 255) / 256, 256>>>(
        out, sbuf + 3 * 128, sbuf + 4 * 128,
        mug, mubeta, lvg, lvbeta, invN, total4);
}

// round 15
// speedup vs baseline: 1.1415x; 1.1415x over previous
#include <cuda_runtime.h>
#include <cuda_fp16.h>
#include <cstddef>
#include <cstdint>

#define D 64
#define NMAX 100000
#define EMAX 1300000
#define HP 36   // half2 pitch per row: bank = 4*gid + tg -> conflict-free

// Scratch (no allocation allowed -> device globals)
__device__ float  g_h[(size_t)NMAX * D];
__device__ float  g_t2[(size_t)NMAX * D];
__device__ float  g_stats[5 * 2 * D];
__device__ int    g_deg[NMAX];
__device__ int    g_ptr[NMAX + 1];
__device__ int    g_cur[NMAX];
__device__ int    g_csr[EMAX];
__device__ int    g_bsum[64];

// ---------------------------------------------------------------------------
__global__ void zero_kernel(int n) {
    int i = blockIdx.x * blockDim.x + threadIdx.x;
    if (i < 5 * 2 * D) g_stats[i] = 0.f;
    if (i < n) g_deg[i] = 0;
}
__global__ void hist_kernel(const int* __restrict__ ei, int E) {
    int e = blockIdx.x * blockDim.x + threadIdx.x;
    if (e < E) atomicAdd(g_deg + __ldg(ei + E + e), 1);
}
__global__ void scan1_kernel(int n) {
    __shared__ int wsum[16];
    int b = blockIdx.x, t = threadIdx.x;
    int lane = t & 31, w = t >> 5;
    int base = b * 2048 + t * 4;
    int v0 = 0, v1 = 0, v2 = 0, v3 = 0;
    if (base + 0 < n) v0 = g_deg[base + 0];
    if (base + 1 < n) v1 = g_deg[base + 1];
    if (base + 2 < n) v2 = g_deg[base + 2];
    if (base + 3 < n) v3 = g_deg[base + 3];
    int s = v0 + v1 + v2 + v3;
    int sc = s;
#pragma unroll
    for (int o = 1; o < 32; o <<= 1) {
        int x = __shfl_up_sync(0xffffffffu, sc, o);
        if (lane >= o) sc += x;
    }
    if (lane == 31) wsum[w] = sc;
    __syncthreads();
    if (w == 0) {
        int ws = (lane < 16) ? wsum[lane] : 0;
#pragma unroll
        for (int o = 1; o < 16; o <<= 1) {
            int x = __shfl_up_sync(0xffffffffu, ws, o);
            if (lane >= o) ws += x;
        }
        if (lane < 16) wsum[lane] = ws;
    }
    __syncthreads();
    int excl = sc - s + (w ? wsum[w - 1] : 0);
    if (base + 0 < n) g_ptr[base + 0] = excl;
    if (base + 1 < n) g_ptr[base + 1] = excl + v0;
    if (base + 2 < n) g_ptr[base + 2] = excl + v0 + v1;
    if (base + 3 < n) g_ptr[base + 3] = excl + v0 + v1 + v2;
    if (t == 511) g_bsum[b] = wsum[15];
}
__global__ void scan2_kernel(int nb) {
    __shared__ int sm[64];
    int t = threadIdx.x;
    sm[t] = (t < nb) ? g_bsum[t] : 0;
    __syncthreads();
    if (t == 0) {
        int run = 0;
        for (int i = 0; i < nb; i++) { int x = sm[i]; sm[i] = run; run += x; }
    }
    __syncthreads();
    if (t < nb) g_bsum[t] = sm[t];
}
__global__ void scan3_kernel(int n, int E) {
    int i = blockIdx.x * blockDim.x + threadIdx.x;
    if (i < n) {
        int p = g_ptr[i] + g_bsum[i >> 11];
        g_ptr[i] = p;
        g_cur[i] = p;
    }
    if (i == n) g_ptr[n] = E;
}
__global__ void fill_kernel(const int* __restrict__ ei, int E) {
    int e = blockIdx.x * blockDim.x + threadIdx.x;
    if (e >= E) return;
    int src = __ldg(ei + e);
    int dst = __ldg(ei + E + e);
    int pos = atomicAdd(g_cur + dst, 1);
    g_csr[pos] = src;
}

// ---------------------------------------------------------------------------
// fp16 split helpers (hi/lo -> ~2^-22 combined mantissa)
__device__ __forceinline__ void split_h2(float x, float y, uint32_t& hi, uint32_t& lo) {
    __half hx = __float2half_rn(x), hy = __float2half_rn(y);
    __half lx = __float2half_rn(x - __half2float(hx));
    __half ly = __float2half_rn(y - __half2float(hy));
    __half2 h = __halves2half2(hx, hy), l = __halves2half2(lx, ly);
    hi = *(uint32_t*)&h; lo = *(uint32_t*)&l;
}
__device__ __forceinline__ void mma_f16(float* c, const uint32_t* a, const uint32_t* b) {
    asm volatile(
        "mma.sync.aligned.m16n8k16.row.col.f32.f16.f16.f32 "
        "{%0,%1,%2,%3}, {%4,%5,%6,%7}, {%8,%9}, {%0,%1,%2,%3};"
        : "+f"(c[0]), "+f"(c[1]), "+f"(c[2]), "+f"(c[3])
        : "r"(a[0]), "r"(a[1]), "r"(a[2]), "r"(a[3]), "r"(b[0]), "r"(b[1]));
}

__device__ __forceinline__ void load_wfrags(
    const float* __restrict__ W, int wn, int gid, int tg,
    uint32_t wh[2][4][2], uint32_t wl[2][4][2])
{
#pragma unroll
    for (int nt = 0; nt < 2; nt++) {
        int col = wn * 16 + nt * 8 + gid;
#pragma unroll
        for (int s = 0; s < 4; s++) {
            int k0 = s * 16 + 2 * tg;
            float w0 = __ldg(W + (k0 + 0) * 64 + col);
            float w1 = __ldg(W + (k0 + 1) * 64 + col);
            float w2 = __ldg(W + (k0 + 8) * 64 + col);
            float w3 = __ldg(W + (k0 + 9) * 64 + col);
            split_h2(w0, w1, wh[nt][s][0], wl[nt][s][0]);
            split_h2(w2, w3, wh[nt][s][1], wl[nt][s][1]);
        }
    }
}

__device__ __forceinline__ void gemm_f16x2(
    const uint32_t* __restrict__ sAh, const uint32_t* __restrict__ sAl,
    int wm, int gid, int tg,
    const uint32_t wh[2][4][2], const uint32_t wl[2][4][2],
    float acc[2][2][4])
{
#pragma unroll
    for (int s = 0; s < 4; s++) {
        uint32_t ah[2][4], al[2][4];
#pragma unroll
        for (int mt = 0; mt < 2; mt++) {
            int r = wm * 32 + mt * 16 + gid;
            int kb = s * 8 + tg;
            ah[mt][0] = sAh[r * HP + kb];
            ah[mt][1] = sAh[(r + 8) * HP + kb];
            ah[mt][2] = sAh[r * HP + kb + 4];
            ah[mt][3] = sAh[(r + 8) * HP + kb + 4];
            al[mt][0] = sAl[r * HP + kb];
            al[mt][1] = sAl[(r + 8) * HP + kb];
            al[mt][2] = sAl[r * HP + kb + 4];
            al[mt][3] = sAl[(r + 8) * HP + kb + 4];
        }
#pragma unroll
        for (int mt = 0; mt < 2; mt++)
#pragma unroll
            for (int nt = 0; nt < 2; nt++) {
                mma_f16(acc[mt][nt], ah[mt], wh[nt][s]);
                mma_f16(acc[mt][nt], al[mt], wh[nt][s]);
                mma_f16(acc[mt][nt], ah[mt], wl[nt][s]);
            }
    }
}

// shared epilogue: bias + relu + store + BN-stat atomics
__device__ __forceinline__ void epilogue(
    float acc[2][2][4], const float* __restrict__ bias,
    float* __restrict__ outF, float* __restrict__ stats,
    int row0, int wm, int wn, int gid, int tg, int nrows)
{
    float cs[2][2] = {{0.f, 0.f}, {0.f, 0.f}};
    float cq[2][2] = {{0.f, 0.f}, {0.f, 0.f}};
#pragma unroll
    for (int nt = 0; nt < 2; nt++) {
        int cb = wn * 16 + nt * 8 + 2 * tg;
        float bx = __ldg(bias + cb), by = __ldg(bias + cb + 1);
#pragma unroll
        for (int mt = 0; mt < 2; mt++) {
#pragma unroll
            for (int hh = 0; hh < 2; hh++) {
                int gr = row0 + wm * 32 + mt * 16 + gid + hh * 8;
                if (gr < nrows) {
                    float ox = fmaxf(acc[mt][nt][2 * hh + 0] + bx, 0.f);
                    float oy = fmaxf(acc[mt][nt][2 * hh + 1] + by, 0.f);
                    *(float2*)(outF + (size_t)gr * D + cb) = make_float2(ox, oy);
                    cs[nt][0] += ox; cq[nt][0] += ox * ox;
                    cs[nt][1] += oy; cq[nt][1] += oy * oy;
                }
            }
        }
    }
#pragma unroll
    for (int off = 4; off < 32; off <<= 1) {
#pragma unroll
        for (int nt = 0; nt < 2; nt++)
#pragma unroll
            for (int j = 0; j < 2; j++) {
                cs[nt][j] += __shfl_xor_sync(0xffffffffu, cs[nt][j], off);
                cq[nt][j] += __shfl_xor_sync(0xffffffffu, cq[nt][j], off);
            }
    }
    if (gid == 0) {
#pragma unroll
        for (int nt = 0; nt < 2; nt++) {
            int c = wn * 16 + nt * 8 + 2 * tg;
            atomicAdd(stats + c,         cs[nt][0]);
            atomicAdd(stats + c + 1,     cs[nt][1]);
            atomicAdd(stats + D + c,     cq[nt][0]);
            atomicAdd(stats + D + c + 1, cq[nt][1]);
        }
    }
}

// ---------------------------------------------------------------------------
// Fused gather + 2-layer MLP via split-fp16 tensor-core GEMM.
__global__ void __launch_bounds__(256, 3) mlp_kernel(
    const float* __restrict__ feat,
    const float* __restrict__ pstats, const float* __restrict__ pg,
    const float* __restrict__ pb,
    const float* __restrict__ W1, const float* __restrict__ b1,
    const float* __restrict__ W2, const float* __restrict__ b2,
    float* __restrict__ outF,
    float* __restrict__ stats, float invN, int nrows)
{
    __shared__ uint32_t sAh[64 * HP];
    __shared__ uint32_t sAl[64 * HP];
    __shared__ float    sAff[2 * D];

    const int t = threadIdx.x;
    const int lane = t & 31, wid = t >> 5;
    const int wm = wid & 1, wn = wid >> 1;
    const int gid = lane >> 2, tg = lane & 3;
    const int row0 = blockIdx.x * 64;
    const bool useAff = (pstats != nullptr);

    if (useAff && t < D) {
        float m  = pstats[t] * invN;
        float var = pstats[D + t] * invN - m * m;
        float sc = pg[t] * rsqrtf(var + 1e-5f);
        sAff[t]     = sc;
        sAff[D + t] = pb[t] - m * sc;
    }
    if (useAff) __syncthreads();

    // fused CSR gather from fp32 features, 16 lanes/node, 4x pipelined
    // with 16B-aligned int4 index loads
#pragma unroll
    for (int pass = 0; pass < 4; pass++) {
        int r = pass * 16 + (t >> 4);
        int node = row0 + r;
        int c4 = (t & 15) << 2;
        float4 acc = make_float4(0.f, 0.f, 0.f, 0.f);
        if (node < nrows) {
            acc = *(const float4*)(feat + (size_t)node * D + c4);
            int s = __ldg(g_ptr + node), e = __ldg(g_ptr + node + 1);
            int j = s;
            // head: singles until j is 4-aligned
            int head = (4 - (j & 3)) & 3;
            if (head > e - j) head = e - j;
            for (int q = 0; q < head; q++, j++) {
                int sv = __ldg(g_csr + j);
                float4 v = *(const float4*)(feat + (size_t)sv * D + c4);
                acc.x += v.x; acc.y += v.y; acc.z += v.z; acc.w += v.w;
            }
            // aligned 4-batches: one LDG.128 for 4 indices
            for (; j + 4 <= e; j += 4) {
                int4 si = *(const int4*)(g_csr + j);
                float4 v0 = *(const float4*)(feat + (size_t)si.x * D + c4);
                float4 v1 = *(const float4*)(feat + (size_t)si.y * D + c4);
                float4 v2 = *(const float4*)(feat + (size_t)si.z * D + c4);
                float4 v3 = *(const float4*)(feat + (size_t)si.w * D + c4);
                acc.x += v0.x + v1.x + v2.x + v3.x;
                acc.y += v0.y + v1.y + v2.y + v3.y;
                acc.z += v0.z + v1.z + v2.z + v3.z;
                acc.w += v0.w + v1.w + v2.w + v3.w;
            }
            // tail singles
            for (; j < e; j++) {
                int sv = __ldg(g_csr + j);
                float4 v = *(const float4*)(feat + (size_t)sv * D + c4);
                acc.x += v.x; acc.y += v.y; acc.z += v.z; acc.w += v.w;
            }
            if (useAff) {
                float cnt = (float)(e - s + 1);
                acc.x = sAff[c4 + 0] * acc.x + cnt * sAff[D + c4 + 0];
                acc.y = sAff[c4 + 1] * acc.y + cnt * sAff[D + c4 + 1];
                acc.z = sAff[c4 + 2] * acc.z + cnt * sAff[D + c4 + 2];
                acc.w = sAff[c4 + 3] * acc.w + cnt * sAff[D + c4 + 3];
            }
        }
        int idx = r * HP + (c4 >> 1);
        split_h2(acc.x, acc.y, sAh[idx], sAl[idx]);
        split_h2(acc.z, acc.w, sAh[idx + 1], sAl[idx + 1]);
    }

    uint32_t wh[2][4][2], wl[2][4][2];
    load_wfrags(W1, wn, gid, tg, wh, wl);

    float acc[2][2][4];
#pragma unroll
    for (int mt = 0; mt < 2; mt++)
#pragma unroll
        for (int nt = 0; nt < 2; nt++)
#pragma unroll
            for (int i = 0; i < 4; i++) acc[mt][nt][i] = 0.f;

    __syncthreads();
    gemm_f16x2(sAh, sAl, wm, gid, tg, wh, wl, acc);

    __syncthreads();
#pragma unroll
    for (int nt = 0; nt < 2; nt++) {
        int cb = wn * 16 + nt * 8 + 2 * tg;
        float bx = __ldg(b1 + cb), by = __ldg(b1 + cb + 1);
        int ci = (cb >> 1);
#pragma unroll
        for (int mt = 0; mt < 2; mt++) {
#pragma unroll
            for (int hh = 0; hh < 2; hh++) {
                int r = wm * 32 + mt * 16 + gid + hh * 8;
                float ox = fmaxf(acc[mt][nt][2 * hh + 0] + bx, 0.f);
                float oy = fmaxf(acc[mt][nt][2 * hh + 1] + by, 0.f);
                split_h2(ox, oy, sAh[r * HP + ci], sAl[r * HP + ci]);
            }
        }
    }
    load_wfrags(W2, wn, gid, tg, wh, wl);
#pragma unroll
    for (int mt = 0; mt < 2; mt++)
#pragma unroll
        for (int nt = 0; nt < 2; nt++)
#pragma unroll
            for (int i = 0; i < 4; i++) acc[mt][nt][i] = 0.f;
    __syncthreads();
    gemm_f16x2(sAh, sAl, wm, gid, tg, wh, wl, acc);

    epilogue(acc, b2, outF, stats, row0, wm, wn, gid, tg, nrows);
}

// ---------------------------------------------------------------------------
// Heads kernel: load t2 tile + BN-3 affine (dense), then BOTH head GEMMs.
__global__ void __launch_bounds__(256, 3) heads_kernel(
    const float* __restrict__ feat,
    const float* __restrict__ pstats, const float* __restrict__ pg,
    const float* __restrict__ pb,
    const float* __restrict__ muW, const float* __restrict__ mub,
    const float* __restrict__ lvW, const float* __restrict__ lvb,
    float* __restrict__ out,
    float* __restrict__ statsMu, float* __restrict__ statsLv,
    float invN, int nrows)
{
    __shared__ uint32_t sAh[64 * HP];
    __shared__ uint32_t sAl[64 * HP];
    __shared__ float    sAff[2 * D];

    const int t = threadIdx.x;
    const int lane = t & 31, wid = t >> 5;
    const int wm = wid & 1, wn = wid >> 1;
    const int gid = lane >> 2, tg = lane & 3;
    const int row0 = blockIdx.x * 64;

    if (t < D) {
        float m  = pstats[t] * invN;
        float var = pstats[D + t] * invN - m * m;
        float sc = pg[t] * rsqrtf(var + 1e-5f);
        sAff[t]     = sc;
        sAff[D + t] = pb[t] - m * sc;
    }
    __syncthreads();

    for (int i = t; i < 1024; i += 256) {
        int r = i >> 4, k4 = (i & 15) << 2;
        float4 v = make_float4(0.f, 0.f, 0.f, 0.f);
        if (row0 + r < nrows) {
            v = *(const float4*)(feat + (size_t)(row0 + r) * D + k4);
            v.x = sAff[k4 + 0] * v.x + sAff[D + k4 + 0];
            v.y = sAff[k4 + 1] * v.y + sAff[D + k4 + 1];
            v.z = sAff[k4 + 2] * v.z + sAff[D + k4 + 2];
            v.w = sAff[k4 + 3] * v.w + sAff[D + k4 + 3];
        }
        int idx = r * HP + (k4 >> 1);
        split_h2(v.x, v.y, sAh[idx], sAl[idx]);
        split_h2(v.z, v.w, sAh[idx + 1], sAl[idx + 1]);
    }

    uint32_t wh[2][4][2], wl[2][4][2];
    float acc[2][2][4];

    // mu head
    load_wfrags(muW, wn, gid, tg, wh, wl);
#pragma unroll
    for (int mt = 0; mt < 2; mt++)
#pragma unroll
        for (int nt = 0; nt < 2; nt++)
#pragma unroll
            for (int i = 0; i < 4; i++) acc[mt][nt][i] = 0.f;
    __syncthreads();
    gemm_f16x2(sAh, sAl, wm, gid, tg, wh, wl, acc);
    epilogue(acc, mub, out, statsMu, row0, wm, wn, gid, tg, nrows);

    // lv head (sA unchanged, read-only)
    load_wfrags(lvW, wn, gid, tg, wh, wl);
#pragma unroll
    for (int mt = 0; mt < 2; mt++)
#pragma unroll
        for (int nt = 0; nt < 2; nt++)
#pragma unroll
            for (int i = 0; i < 4; i++) acc[mt][nt][i] = 0.f;
    gemm_f16x2(sAh, sAl, wm, gid, tg, wh, wl, acc);
    epilogue(acc, lvb, out + (size_t)nrows * D, statsLv,
             row0, wm, wn, gid, tg, nrows);
}

// ---------------------------------------------------------------------------
// final BN for both halves of out, in place
__global__ void bn2_apply_kernel(float* __restrict__ out,
                                 const float* __restrict__ statsMu,
                                 const float* __restrict__ statsLv,
                                 const float* __restrict__ mug,
                                 const float* __restrict__ mubeta,
                                 const float* __restrict__ lvg,
                                 const float* __restrict__ lvbeta,
                                 float invN, int total4)
{
    int i = blockIdx.x * blockDim.x + threadIdx.x;
    if (i >= 2 * total4) return;
    bool isLv = (i >= total4);
    const float* stats = isLv ? statsLv : statsMu;
    const float* g = isLv ? lvg : mug;
    const float* b = isLv ? lvbeta : mubeta;
    int c = (i << 2) & 63;
    float4 v = ((const float4*)out)[i];
    float4 y;
#pragma unroll
    for (int j = 0; j < 4; j++) {
        float m  = stats[c + j] * invN;
        float var = stats[D + c + j] * invN - m * m;
        float sc = g[c + j] * rsqrtf(var + 1e-5f);
        float sh = b[c + j] - m * sc;
        (&y.x)[j] = (&v.x)[j] * sc + sh;
    }
    ((float4*)out)[i] = y;
}

// ---------------------------------------------------------------------------
extern "C" void kernel_launch(void* const* d_in, const int* in_sizes, int n_in,
                              void* d_out, int out_size)
{
    const float* x      = (const float*)d_in[0];
    const int*   ei     = (const int*)d_in[1];   // int32 (JAX downcast)
    const float* W1     = (const float*)d_in[3];
    const float* b1     = (const float*)d_in[4];
    const float* W2     = (const float*)d_in[5];
    const float* b2     = (const float*)d_in[6];
    const float* bng    = (const float*)d_in[7];
    const float* bnb    = (const float*)d_in[8];
    const float* muW    = (const float*)d_in[9];
    const float* mub    = (const float*)d_in[10];
    const float* lvW    = (const float*)d_in[11];
    const float* lvb    = (const float*)d_in[12];
    const float* mug    = (const float*)d_in[13];
    const float* mubeta = (const float*)d_in[14];
    const float* lvg    = (const float*)d_in[15];
    const float* lvbeta = (const float*)d_in[16];
    float* out = (float*)d_out;

    const int n = in_sizes[0] / D;
    const int E = in_sizes[1] / 2;
    const float invN = 1.0f / (float)n;
    const int total4 = n * (D / 4);
    const int gb = (n + 63) / 64;
    const int ebE = (E + 255) / 256;
    const int nb_scan = (n + 2047) / 2048;

    float *hbuf, *tbuf, *sbuf;
    cudaGetSymbolAddress((void**)&hbuf, g_h);
    cudaGetSymbolAddress((void**)&tbuf, g_t2);
    cudaGetSymbolAddress((void**)&sbuf, g_stats);

    zero_kernel<<<(n + 255) / 256, 256>>>(n);

    // build CSR (dst -> list of src)
    hist_kernel<<<ebE, 256>>>(ei, E);
    scan1_kernel<<<nb_scan, 512>>>(n);
    scan2_kernel<<<1, 64>>>(nb_scan);
    scan3_kernel<<<(n + 256) / 256, 256>>>(n, E);
    fill_kernel<<<ebE, 256>>>(ei, E);

    // layer 1: gather x, no affine -> t2 (pre-BN, fp32)
    mlp_kernel<<<gb, 256>>>(
        x, nullptr, nullptr, nullptr,
        W1, b1, W2, b2, tbuf, sbuf, invN, n);
    // layer 2: gather t2 + layer-1 affine -> h
    mlp_kernel<<<gb, 256>>>(
        tbuf, sbuf, bng, bnb,
        W1 + 4096, b1 + 64, W2 + 4096, b2 + 64, hbuf, sbuf + 128, invN, n);
    // layer 3: gather h + layer-2 affine -> t2
    mlp_kernel<<<gb, 256>>>(
        hbuf, sbuf + 128, bng + 64, bnb + 64,
        W1 + 8192, b1 + 128, W2 + 8192, b2 + 128, tbuf, sbuf + 256, invN, n);

    // heads: BN-3 affine fused into tile load; both GEMMs; pre-BN -> out
    heads_kernel<<<gb, 256>>>(
        tbuf, sbuf + 256, bng + 128, bnb + 128,
        muW, mub, lvW, lvb, out, sbuf + 3 * 128, sbuf + 4 * 128, invN, n);

    // final BN on both halves (in place)
    bn2_apply_kernel<<<(2 * total4 + 255) / 256, 256>>>(
        out, sbuf + 3 * 128, sbuf + 4 * 128,
        mug, mubeta, lvg, lvbeta, invN, total4);
}

// round 16
// speedup vs baseline: 1.2013x; 1.0524x over previous
#include <cuda_runtime.h>
#include <cuda_fp16.h>
#include <cstddef>
#include <cstdint>

#define D 64
#define NMAX 100000
#define EMAX 1300000
#define HP 36   // half2 pitch per row: bank = 4*gid + tg -> conflict-free

// Scratch (no allocation allowed -> device globals)
__device__ float  g_h[(size_t)NMAX * D];
__device__ float  g_t2[(size_t)NMAX * D];
__device__ float  g_stats[5 * 2 * D];
__device__ int    g_deg[NMAX];
__device__ int    g_ptr[NMAX + 1];
__device__ int    g_cur[NMAX];
__device__ int    g_csr[EMAX];
__device__ int    g_bsum[64];

// ---------------------------------------------------------------------------
__global__ void zero_kernel(int n) {
    int i = blockIdx.x * blockDim.x + threadIdx.x;
    if (i < 5 * 2 * D) g_stats[i] = 0.f;
    if (i < n) g_deg[i] = 0;
}
// 4 edges per thread: 4 independent atomics in flight (ATOMG latency hiding)
__global__ void hist_kernel(const int* __restrict__ ei, int E) {
    int e0 = (blockIdx.x * blockDim.x + threadIdx.x) * 4;
#pragma unroll
    for (int q = 0; q < 4; q++) {
        int e = e0 + q;
        if (e < E) atomicAdd(g_deg + __ldg(ei + E + e), 1);
    }
}
__global__ void scan1_kernel(int n) {
    __shared__ int wsum[16];
    int b = blockIdx.x, t = threadIdx.x;
    int lane = t & 31, w = t >> 5;
    int base = b * 2048 + t * 4;
    int v0 = 0, v1 = 0, v2 = 0, v3 = 0;
    if (base + 0 < n) v0 = g_deg[base + 0];
    if (base + 1 < n) v1 = g_deg[base + 1];
    if (base + 2 < n) v2 = g_deg[base + 2];
    if (base + 3 < n) v3 = g_deg[base + 3];
    int s = v0 + v1 + v2 + v3;
    int sc = s;
#pragma unroll
    for (int o = 1; o < 32; o <<= 1) {
        int x = __shfl_up_sync(0xffffffffu, sc, o);
        if (lane >= o) sc += x;
    }
    if (lane == 31) wsum[w] = sc;
    __syncthreads();
    if (w == 0) {
        int ws = (lane < 16) ? wsum[lane] : 0;
#pragma unroll
        for (int o = 1; o < 16; o <<= 1) {
            int x = __shfl_up_sync(0xffffffffu, ws, o);
            if (lane >= o) ws += x;
        }
        if (lane < 16) wsum[lane] = ws;
    }
    __syncthreads();
    int excl = sc - s + (w ? wsum[w - 1] : 0);
    if (base + 0 < n) g_ptr[base + 0] = excl;
    if (base + 1 < n) g_ptr[base + 1] = excl + v0;
    if (base + 2 < n) g_ptr[base + 2] = excl + v0 + v1;
    if (base + 3 < n) g_ptr[base + 3] = excl + v0 + v1 + v2;
    if (t == 511) g_bsum[b] = wsum[15];
}
__global__ void scan2_kernel(int nb) {
    __shared__ int sm[64];
    int t = threadIdx.x;
    sm[t] = (t < nb) ? g_bsum[t] : 0;
    __syncthreads();
    if (t == 0) {
        int run = 0;
        for (int i = 0; i < nb; i++) { int x = sm[i]; sm[i] = run; run += x; }
    }
    __syncthreads();
    if (t < nb) g_bsum[t] = sm[t];
}
__global__ void scan3_kernel(int n, int E) {
    int i = blockIdx.x * blockDim.x + threadIdx.x;
    if (i < n) {
        int p = g_ptr[i] + g_bsum[i >> 11];
        g_ptr[i] = p;
        g_cur[i] = p;
    }
    if (i == n) g_ptr[n] = E;
}
// 4 edges per thread: 4 independent atomic+store chains in flight
__global__ void fill_kernel(const int* __restrict__ ei, int E) {
    int e0 = (blockIdx.x * blockDim.x + threadIdx.x) * 4;
    int src[4], pos[4];
#pragma unroll
    for (int q = 0; q < 4; q++) {
        int e = e0 + q;
        if (e < E) {
            src[q] = __ldg(ei + e);
            int dst = __ldg(ei + E + e);
            pos[q] = atomicAdd(g_cur + dst, 1);
        }
    }
#pragma unroll
    for (int q = 0; q < 4; q++) {
        int e = e0 + q;
        if (e < E) g_csr[pos[q]] = src[q];
    }
}

// ---------------------------------------------------------------------------
// fp16 split helpers (hi/lo -> ~2^-22 combined mantissa)
__device__ __forceinline__ void split_h2(float x, float y, uint32_t& hi, uint32_t& lo) {
    __half hx = __float2half_rn(x), hy = __float2half_rn(y);
    __half lx = __float2half_rn(x - __half2float(hx));
    __half ly = __float2half_rn(y - __half2float(hy));
    __half2 h = __halves2half2(hx, hy), l = __halves2half2(lx, ly);
    hi = *(uint32_t*)&h; lo = *(uint32_t*)&l;
}
__device__ __forceinline__ void mma_f16(float* c, const uint32_t* a, const uint32_t* b) {
    asm volatile(
        "mma.sync.aligned.m16n8k16.row.col.f32.f16.f16.f32 "
        "{%0,%1,%2,%3}, {%4,%5,%6,%7}, {%8,%9}, {%0,%1,%2,%3};"
        : "+f"(c[0]), "+f"(c[1]), "+f"(c[2]), "+f"(c[3])
        : "r"(a[0]), "r"(a[1]), "r"(a[2]), "r"(a[3]), "r"(b[0]), "r"(b[1]));
}

__device__ __forceinline__ void load_wfrags(
    const float* __restrict__ W, int wn, int gid, int tg,
    uint32_t wh[2][4][2], uint32_t wl[2][4][2])
{
#pragma unroll
    for (int nt = 0; nt < 2; nt++) {
        int col = wn * 16 + nt * 8 + gid;
#pragma unroll
        for (int s = 0; s < 4; s++) {
            int k0 = s * 16 + 2 * tg;
            float w0 = __ldg(W + (k0 + 0) * 64 + col);
            float w1 = __ldg(W + (k0 + 1) * 64 + col);
            float w2 = __ldg(W + (k0 + 8) * 64 + col);
            float w3 = __ldg(W + (k0 + 9) * 64 + col);
            split_h2(w0, w1, wh[nt][s][0], wl[nt][s][0]);
            split_h2(w2, w3, wh[nt][s][1], wl[nt][s][1]);
        }
    }
}

__device__ __forceinline__ void gemm_f16x2(
    const uint32_t* __restrict__ sAh, const uint32_t* __restrict__ sAl,
    int wm, int gid, int tg,
    const uint32_t wh[2][4][2], const uint32_t wl[2][4][2],
    float acc[2][2][4])
{
#pragma unroll
    for (int s = 0; s < 4; s++) {
        uint32_t ah[2][4], al[2][4];
#pragma unroll
        for (int mt = 0; mt < 2; mt++) {
            int r = wm * 32 + mt * 16 + gid;
            int kb = s * 8 + tg;
            ah[mt][0] = sAh[r * HP + kb];
            ah[mt][1] = sAh[(r + 8) * HP + kb];
            ah[mt][2] = sAh[r * HP + kb + 4];
            ah[mt][3] = sAh[(r + 8) * HP + kb + 4];
            al[mt][0] = sAl[r * HP + kb];
            al[mt][1] = sAl[(r + 8) * HP + kb];
            al[mt][2] = sAl[r * HP + kb + 4];
            al[mt][3] = sAl[(r + 8) * HP + kb + 4];
        }
#pragma unroll
        for (int mt = 0; mt < 2; mt++)
#pragma unroll
            for (int nt = 0; nt < 2; nt++) {
                mma_f16(acc[mt][nt], ah[mt], wh[nt][s]);
                mma_f16(acc[mt][nt], al[mt], wh[nt][s]);
                mma_f16(acc[mt][nt], ah[mt], wl[nt][s]);
            }
    }
}

// shared epilogue: bias + relu + store + BN-stat atomics
__device__ __forceinline__ void epilogue(
    float acc[2][2][4], const float* __restrict__ bias,
    float* __restrict__ outF, float* __restrict__ stats,
    int row0, int wm, int wn, int gid, int tg, int nrows)
{
    float cs[2][2] = {{0.f, 0.f}, {0.f, 0.f}};
    float cq[2][2] = {{0.f, 0.f}, {0.f, 0.f}};
#pragma unroll
    for (int nt = 0; nt < 2; nt++) {
        int cb = wn * 16 + nt * 8 + 2 * tg;
        float bx = __ldg(bias + cb), by = __ldg(bias + cb + 1);
#pragma unroll
        for (int mt = 0; mt < 2; mt++) {
#pragma unroll
            for (int hh = 0; hh < 2; hh++) {
                int gr = row0 + wm * 32 + mt * 16 + gid + hh * 8;
                if (gr < nrows) {
                    float ox = fmaxf(acc[mt][nt][2 * hh + 0] + bx, 0.f);
                    float oy = fmaxf(acc[mt][nt][2 * hh + 1] + by, 0.f);
                    *(float2*)(outF + (size_t)gr * D + cb) = make_float2(ox, oy);
                    cs[nt][0] += ox; cq[nt][0] += ox * ox;
                    cs[nt][1] += oy; cq[nt][1] += oy * oy;
                }
            }
        }
    }
#pragma unroll
    for (int off = 4; off < 32; off <<= 1) {
#pragma unroll
        for (int nt = 0; nt < 2; nt++)
#pragma unroll
            for (int j = 0; j < 2; j++) {
                cs[nt][j] += __shfl_xor_sync(0xffffffffu, cs[nt][j], off);
                cq[nt][j] += __shfl_xor_sync(0xffffffffu, cq[nt][j], off);
            }
    }
    if (gid == 0) {
#pragma unroll
        for (int nt = 0; nt < 2; nt++) {
            int c = wn * 16 + nt * 8 + 2 * tg;
            atomicAdd(stats + c,         cs[nt][0]);
            atomicAdd(stats + c + 1,     cs[nt][1]);
            atomicAdd(stats + D + c,     cq[nt][0]);
            atomicAdd(stats + D + c + 1, cq[nt][1]);
        }
    }
}

// ---------------------------------------------------------------------------
// Fused gather + 2-layer MLP via split-fp16 tensor-core GEMM.
__global__ void __launch_bounds__(256, 3) mlp_kernel(
    const float* __restrict__ feat,
    const float* __restrict__ pstats, const float* __restrict__ pg,
    const float* __restrict__ pb,
    const float* __restrict__ W1, const float* __restrict__ b1,
    const float* __restrict__ W2, const float* __restrict__ b2,
    float* __restrict__ outF,
    float* __restrict__ stats, float invN, int nrows)
{
    __shared__ uint32_t sAh[64 * HP];
    __shared__ uint32_t sAl[64 * HP];
    __shared__ float    sAff[2 * D];

    const int t = threadIdx.x;
    const int lane = t & 31, wid = t >> 5;
    const int wm = wid & 1, wn = wid >> 1;
    const int gid = lane >> 2, tg = lane & 3;
    const int row0 = blockIdx.x * 64;
    const bool useAff = (pstats != nullptr);

    if (useAff && t < D) {
        float m  = pstats[t] * invN;
        float var = pstats[D + t] * invN - m * m;
        float sc = pg[t] * rsqrtf(var + 1e-5f);
        sAff[t]     = sc;
        sAff[D + t] = pb[t] - m * sc;
    }
    if (useAff) __syncthreads();

    // fused CSR gather from fp32 features, 16 lanes/node, 4x pipelined
#pragma unroll
    for (int pass = 0; pass < 4; pass++) {
        int r = pass * 16 + (t >> 4);
        int node = row0 + r;
        int c4 = (t & 15) << 2;
        float4 acc = make_float4(0.f, 0.f, 0.f, 0.f);
        if (node < nrows) {
            acc = *(const float4*)(feat + (size_t)node * D + c4);
            int s = __ldg(g_ptr + node), e = __ldg(g_ptr + node + 1);
            int j = s;
            for (; j + 4 <= e; j += 4) {
                int s0 = __ldg(g_csr + j + 0);
                int s1 = __ldg(g_csr + j + 1);
                int s2 = __ldg(g_csr + j + 2);
                int s3 = __ldg(g_csr + j + 3);
                float4 v0 = *(const float4*)(feat + (size_t)s0 * D + c4);
                float4 v1 = *(const float4*)(feat + (size_t)s1 * D + c4);
                float4 v2 = *(const float4*)(feat + (size_t)s2 * D + c4);
                float4 v3 = *(const float4*)(feat + (size_t)s3 * D + c4);
                acc.x += v0.x + v1.x + v2.x + v3.x;
                acc.y += v0.y + v1.y + v2.y + v3.y;
                acc.z += v0.z + v1.z + v2.z + v3.z;
                acc.w += v0.w + v1.w + v2.w + v3.w;
            }
            for (; j < e; j++) {
                int sv = __ldg(g_csr + j);
                float4 v = *(const float4*)(feat + (size_t)sv * D + c4);
                acc.x += v.x; acc.y += v.y; acc.z += v.z; acc.w += v.w;
            }
            if (useAff) {
                float cnt = (float)(e - s + 1);
                acc.x = sAff[c4 + 0] * acc.x + cnt * sAff[D + c4 + 0];
                acc.y = sAff[c4 + 1] * acc.y + cnt * sAff[D + c4 + 1];
                acc.z = sAff[c4 + 2] * acc.z + cnt * sAff[D + c4 + 2];
                acc.w = sAff[c4 + 3] * acc.w + cnt * sAff[D + c4 + 3];
            }
        }
        int idx = r * HP + (c4 >> 1);
        split_h2(acc.x, acc.y, sAh[idx], sAl[idx]);
        split_h2(acc.z, acc.w, sAh[idx + 1], sAl[idx + 1]);
    }

    uint32_t wh[2][4][2], wl[2][4][2];
    load_wfrags(W1, wn, gid, tg, wh, wl);

    float acc[2][2][4];
#pragma unroll
    for (int mt = 0; mt < 2; mt++)
#pragma unroll
        for (int nt = 0; nt < 2; nt++)
#pragma unroll
            for (int i = 0; i < 4; i++) acc[mt][nt][i] = 0.f;

    __syncthreads();
    gemm_f16x2(sAh, sAl, wm, gid, tg, wh, wl, acc);

    __syncthreads();
#pragma unroll
    for (int nt = 0; nt < 2; nt++) {
        int cb = wn * 16 + nt * 8 + 2 * tg;
        float bx = __ldg(b1 + cb), by = __ldg(b1 + cb + 1);
        int ci = (cb >> 1);
#pragma unroll
        for (int mt = 0; mt < 2; mt++) {
#pragma unroll
            for (int hh = 0; hh < 2; hh++) {
                int r = wm * 32 + mt * 16 + gid + hh * 8;
                float ox = fmaxf(acc[mt][nt][2 * hh + 0] + bx, 0.f);
                float oy = fmaxf(acc[mt][nt][2 * hh + 1] + by, 0.f);
                split_h2(ox, oy, sAh[r * HP + ci], sAl[r * HP + ci]);
            }
        }
    }
    load_wfrags(W2, wn, gid, tg, wh, wl);
#pragma unroll
    for (int mt = 0; mt < 2; mt++)
#pragma unroll
        for (int nt = 0; nt < 2; nt++)
#pragma unroll
            for (int i = 0; i < 4; i++) acc[mt][nt][i] = 0.f;
    __syncthreads();
    gemm_f16x2(sAh, sAl, wm, gid, tg, wh, wl, acc);

    epilogue(acc, b2, outF, stats, row0, wm, wn, gid, tg, nrows);
}

// ---------------------------------------------------------------------------
// Heads kernel: load t2 tile + BN-3 affine (dense), then BOTH head GEMMs.
__global__ void __launch_bounds__(256, 3) heads_kernel(
    const float* __restrict__ feat,
    const float* __restrict__ pstats, const float* __restrict__ pg,
    const float* __restrict__ pb,
    const float* __restrict__ muW, const float* __restrict__ mub,
    const float* __restrict__ lvW, const float* __restrict__ lvb,
    float* __restrict__ out,
    float* __restrict__ statsMu, float* __restrict__ statsLv,
    float invN, int nrows)
{
    __shared__ uint32_t sAh[64 * HP];
    __shared__ uint32_t sAl[64 * HP];
    __shared__ float    sAff[2 * D];

    const int t = threadIdx.x;
    const int lane = t & 31, wid = t >> 5;
    const int wm = wid & 1, wn = wid >> 1;
    const int gid = lane >> 2, tg = lane & 3;
    const int row0 = blockIdx.x * 64;

    if (t < D) {
        float m  = pstats[t] * invN;
        float var = pstats[D + t] * invN - m * m;
        float sc = pg[t] * rsqrtf(var + 1e-5f);
        sAff[t]     = sc;
        sAff[D + t] = pb[t] - m * sc;
    }
    __syncthreads();

    for (int i = t; i < 1024; i += 256) {
        int r = i >> 4, k4 = (i & 15) << 2;
        float4 v = make_float4(0.f, 0.f, 0.f, 0.f);
        if (row0 + r < nrows) {
            v = *(const float4*)(feat + (size_t)(row0 + r) * D + k4);
            v.x = sAff[k4 + 0] * v.x + sAff[D + k4 + 0];
            v.y = sAff[k4 + 1] * v.y + sAff[D + k4 + 1];
            v.z = sAff[k4 + 2] * v.z + sAff[D + k4 + 2];
            v.w = sAff[k4 + 3] * v.w + sAff[D + k4 + 3];
        }
        int idx = r * HP + (k4 >> 1);
        split_h2(v.x, v.y, sAh[idx], sAl[idx]);
        split_h2(v.z, v.w, sAh[idx + 1], sAl[idx + 1]);
    }

    uint32_t wh[2][4][2], wl[2][4][2];
    float acc[2][2][4];

    // mu head
    load_wfrags(muW, wn, gid, tg, wh, wl);
#pragma unroll
    for (int mt = 0; mt < 2; mt++)
#pragma unroll
        for (int nt = 0; nt < 2; nt++)
#pragma unroll
            for (int i = 0; i < 4; i++) acc[mt][nt][i] = 0.f;
    __syncthreads();
    gemm_f16x2(sAh, sAl, wm, gid, tg, wh, wl, acc);
    epilogue(acc, mub, out, statsMu, row0, wm, wn, gid, tg, nrows);

    // lv head (sA unchanged, read-only)
    load_wfrags(lvW, wn, gid, tg, wh, wl);
#pragma unroll
    for (int mt = 0; mt < 2; mt++)
#pragma unroll
        for (int nt = 0; nt < 2; nt++)
#pragma unroll
            for (int i = 0; i < 4; i++) acc[mt][nt][i] = 0.f;
    gemm_f16x2(sAh, sAl, wm, gid, tg, wh, wl, acc);
    epilogue(acc, lvb, out + (size_t)nrows * D, statsLv,
             row0, wm, wn, gid, tg, nrows);
}

// ---------------------------------------------------------------------------
// final BN for both halves of out, in place
__global__ void bn2_apply_kernel(float* __restrict__ out,
                                 const float* __restrict__ statsMu,
                                 const float* __restrict__ statsLv,
                                 const float* __restrict__ mug,
                                 const float* __restrict__ mubeta,
                                 const float* __restrict__ lvg,
                                 const float* __restrict__ lvbeta,
                                 float invN, int total4)
{
    int i = blockIdx.x * blockDim.x + threadIdx.x;
    if (i >= 2 * total4) return;
    bool isLv = (i >= total4);
    const float* stats = isLv ? statsLv : statsMu;
    const float* g = isLv ? lvg : mug;
    const float* b = isLv ? lvbeta : mubeta;
    int c = (i << 2) & 63;
    float4 v = ((const float4*)out)[i];
    float4 y;
#pragma unroll
    for (int j = 0; j < 4; j++) {
        float m  = stats[c + j] * invN;
        float var = stats[D + c + j] * invN - m * m;
        float sc = g[c + j] * rsqrtf(var + 1e-5f);
        float sh = b[c + j] - m * sc;
        (&y.x)[j] = (&v.x)[j] * sc + sh;
    }
    ((float4*)out)[i] = y;
}

// ---------------------------------------------------------------------------
extern "C" void kernel_launch(void* const* d_in, const int* in_sizes, int n_in,
                              void* d_out, int out_size)
{
    const float* x      = (const float*)d_in[0];
    const int*   ei     = (const int*)d_in[1];   // int32 (JAX downcast)
    const float* W1     = (const float*)d_in[3];
    const float* b1     = (const float*)d_in[4];
    const float* W2     = (const float*)d_in[5];
    const float* b2     = (const float*)d_in[6];
    const float* bng    = (const float*)d_in[7];
    const float* bnb    = (const float*)d_in[8];
    const float* muW    = (const float*)d_in[9];
    const float* mub    = (const float*)d_in[10];
    const float* lvW    = (const float*)d_in[11];
    const float* lvb    = (const float*)d_in[12];
    const float* mug    = (const float*)d_in[13];
    const float* mubeta = (const float*)d_in[14];
    const float* lvg    = (const float*)d_in[15];
    const float* lvbeta = (const float*)d_in[16];
    float* out = (float*)d_out;

    const int n = in_sizes[0] / D;
    const int E = in_sizes[1] / 2;
    const float invN = 1.0f / (float)n;
    const int total4 = n * (D / 4);
    const int gb = (n + 63) / 64;
    const int eb4 = (E + 1023) / 1024;   // 4 edges per thread
    const int nb_scan = (n + 2047) / 2048;

    float *hbuf, *tbuf, *sbuf;
    cudaGetSymbolAddress((void**)&hbuf, g_h);
    cudaGetSymbolAddress((void**)&tbuf, g_t2);
    cudaGetSymbolAddress((void**)&sbuf, g_stats);

    zero_kernel<<<(n + 255) / 256, 256>>>(n);

    // build CSR (dst -> list of src)
    hist_kernel<<<eb4, 256>>>(ei, E);
    scan1_kernel<<<nb_scan, 512>>>(n);
    scan2_kernel<<<1, 64>>>(nb_scan);
    scan3_kernel<<<(n + 256) / 256, 256>>>(n, E);
    fill_kernel<<<eb4, 256>>>(ei, E);

    // layer 1: gather x, no affine -> t2 (pre-BN, fp32)
    mlp_kernel<<<gb, 256>>>(
        x, nullptr, nullptr, nullptr,
        W1, b1, W2, b2, tbuf, sbuf, invN, n);
    // layer 2: gather t2 + layer-1 affine -> h
    mlp_kernel<<<gb, 256>>>(
        tbuf, sbuf, bng, bnb,
        W1 + 4096, b1 + 64, W2 + 4096, b2 + 64, hbuf, sbuf + 128, invN, n);
    // layer 3: gather h + layer-2 affine -> t2
    mlp_kernel<<<gb, 256>>>(
        hbuf, sbuf + 128, bng + 64, bnb + 64,
        W1 + 8192, b1 + 128, W2 + 8192, b2 + 128, tbuf, sbuf + 256, invN, n);

    // heads: BN-3 affine fused into tile load; both GEMMs; pre-BN -> out
    heads_kernel<<<gb, 256>>>(
        tbuf, sbuf + 256, bng + 128, bnb + 128,
        muW, mub, lvW, lvb, out, sbuf + 3 * 128, sbuf + 4 * 128, invN, n);

    // final BN on both halves (in place)
    bn2_apply_kernel<<<(2 * total4 + 255) / 256, 256>>>(
        out, sbuf + 3 * 128, sbuf + 4 * 128,
        mug, mubeta, lvg, lvbeta, invN, total4);
}